// round 6
// baseline (speedup 1.0000x reference)
#include <cuda_runtime.h>
#include <cuda_fp16.h>
#include <cstdint>
#include <cstddef>

// ---------------------------------------------------------------------------
// CompressedLinear, legacy-tensor-core edition (harness targets plain sm_100:
// tcgen05/TMEM are 'a'-suffix features and unavailable; mma.sync is the only
// tensor path).
//   out[4096, 11008] = x_f16[4096,4096] @ (w_f16[11008,4096])^T * scale + bias
//
// GEMM: block tile 128(M) x 256(N) x 64(K), 3-stage cp.async pipeline,
// 8 warps, warp tile 64x64, mma.sync.m16n8k16 fp16 -> fp32. 1 CTA/SM.
// ---------------------------------------------------------------------------

namespace {
constexpr int M_DIM = 4096;
constexpr int K_DIM = 4096;
constexpr int N_DIM = 11008;

constexpr int BM = 128;
constexpr int BN = 256;
constexpr int BK = 64;
constexpr int STAGES = 3;
constexpr int NTHREADS = 256;
constexpr int KTILES = K_DIM / BK;                 // 64

constexpr int A_STAGE_BYTES = BM * BK * 2;         // 16 KB
constexpr int B_STAGE_BYTES = BN * BK * 2;         // 32 KB
constexpr int STAGE_BYTES   = A_STAGE_BYTES + B_STAGE_BYTES;   // 48 KB
constexpr int SMEM_BYTES    = STAGES * STAGE_BYTES;            // 144 KB
}

// fp16 scratch (allocation-free rule: __device__ globals)
__device__ __half g_X[(size_t)M_DIM * K_DIM];   // 32 MB [M,K]
__device__ __half g_W[(size_t)N_DIM * K_DIM];   // 90 MB [N,K]

// ---------------------------------------------------------------------------
// Conversion kernels: 4 independent float4/int4 loads per thread (MLP=4)
// ---------------------------------------------------------------------------
__global__ void convert_x_kernel(const float* __restrict__ x) {
    size_t blk = (size_t)blockIdx.x * 4096;       // elements per block
    #pragma unroll
    for (int t = 0; t < 4; ++t) {
        size_t i = blk + (size_t)t * 1024 + threadIdx.x * 4;
        float4 v = *reinterpret_cast<const float4*>(x + i);
        __half2 h0 = __floats2half2_rn(v.x, v.y);
        __half2 h1 = __floats2half2_rn(v.z, v.w);
        uint2 u;
        u.x = reinterpret_cast<uint32_t&>(h0);
        u.y = reinterpret_cast<uint32_t&>(h1);
        *reinterpret_cast<uint2*>(&g_X[i]) = u;
    }
}

__global__ void convert_w_kernel(const int* __restrict__ w) {
    size_t blk = (size_t)blockIdx.x * 4096;
    #pragma unroll
    for (int t = 0; t < 4; ++t) {
        size_t i = blk + (size_t)t * 1024 + threadIdx.x * 4;
        int4 v = *reinterpret_cast<const int4*>(w + i);
        __half2 h0 = __halves2half2(__int2half_rn(v.x), __int2half_rn(v.y));
        __half2 h1 = __halves2half2(__int2half_rn(v.z), __int2half_rn(v.w));
        uint2 u;
        u.x = reinterpret_cast<uint32_t&>(h0);
        u.y = reinterpret_cast<uint32_t&>(h1);
        *reinterpret_cast<uint2*>(&g_W[i]) = u;
    }
}

// ---------------------------------------------------------------------------
// Helpers
// ---------------------------------------------------------------------------
__device__ __forceinline__ uint32_t swz128(uint32_t b) {
    return b ^ ((b >> 3) & 0x70);
}
__device__ __forceinline__ void cp_async16(uint32_t dst, const void* src) {
    asm volatile("cp.async.cg.shared.global [%0], [%1], 16;\n" :: "r"(dst), "l"(src));
}
__device__ __forceinline__ void cp_commit() {
    asm volatile("cp.async.commit_group;\n");
}
template <int N>
__device__ __forceinline__ void cp_wait() {
    asm volatile("cp.async.wait_group %0;\n" :: "n"(N));
}

// ---------------------------------------------------------------------------
// GEMM kernel
// ---------------------------------------------------------------------------
__global__ __launch_bounds__(NTHREADS, 1)
void gemm_kernel(const float* __restrict__ scale_p,
                 const float* __restrict__ bias,
                 float* __restrict__ out) {
    extern __shared__ __align__(128) char smem_raw[];
    const uint32_t smem_base = (uint32_t)__cvta_generic_to_shared(smem_raw);

    const int tid  = threadIdx.x;
    const int warp = tid >> 5;
    const int lane = tid & 31;
    const int bx = blockIdx.x;            // N block (0..42)
    const int by = blockIdx.y;            // M block (0..31)

    const int warp_m = warp & 1;          // 0..1  (64 rows)
    const int warp_n = warp >> 1;         // 0..3  (64 cols)

    const int mRow0 = by * BM;
    const int nCol0 = bx * BN;

    float acc[4][8][4];
    #pragma unroll
    for (int i = 0; i < 4; ++i)
        #pragma unroll
        for (int j = 0; j < 8; ++j)
            #pragma unroll
            for (int k = 0; k < 4; ++k)
                acc[i][j][k] = 0.0f;

    // stage loader: A 1024 chunks (4/thread) + B 2048 chunks (8/thread)
    auto load_stage = [&](int s, int kt) {
        const uint32_t aB = smem_base + s * STAGE_BYTES;
        const uint32_t bB = aB + A_STAGE_BYTES;
        const int k0 = kt * BK;
        #pragma unroll
        for (int t = 0; t < 4; ++t) {
            int c   = tid + t * NTHREADS;      // 0..1023
            int row = c >> 3;                  // 0..127
            int col = c & 7;
            uint32_t off = swz128((uint32_t)(row * 128 + col * 16));
            cp_async16(aB + off, &g_X[(size_t)(mRow0 + row) * K_DIM + k0 + col * 8]);
        }
        #pragma unroll
        for (int t = 0; t < 8; ++t) {
            int c   = tid + t * NTHREADS;      // 0..2047
            int row = c >> 3;                  // 0..255
            int col = c & 7;
            uint32_t off = swz128((uint32_t)(row * 128 + col * 16));
            cp_async16(bB + off, &g_W[(size_t)(nCol0 + row) * K_DIM + k0 + col * 8]);
        }
    };

    auto mma_stage = [&](int s) {
        const uint32_t aB = smem_base + s * STAGE_BYTES;
        const uint32_t bB = aB + A_STAGE_BYTES;
        #pragma unroll
        for (int ks = 0; ks < BK / 16; ++ks) {
            uint32_t af[4][4];
            uint32_t bf[8][2];
            // A: 4 m16k16 tiles via ldmatrix.x4
            #pragma unroll
            for (int mt = 0; mt < 4; ++mt) {
                int r = warp_m * 64 + mt * 16 + (lane & 15);
                uint32_t addr = aB +
                    swz128((uint32_t)(r * 128 + ks * 32 + (lane >> 4) * 16));
                asm volatile(
                    "ldmatrix.sync.aligned.m8n8.x4.shared.b16 {%0,%1,%2,%3}, [%4];\n"
                    : "=r"(af[mt][0]), "=r"(af[mt][1]),
                      "=r"(af[mt][2]), "=r"(af[mt][3])
                    : "r"(addr));
            }
            // B: 8 n8k16 tiles via 4 ldmatrix.x4
            #pragma unroll
            for (int p = 0; p < 4; ++p) {
                int n  = warp_n * 64 + p * 16 + (lane & 7) + ((lane >> 4) << 3);
                int kc = (lane >> 3) & 1;
                uint32_t addr = bB +
                    swz128((uint32_t)(n * 128 + ks * 32 + kc * 16));
                asm volatile(
                    "ldmatrix.sync.aligned.m8n8.x4.shared.b16 {%0,%1,%2,%3}, [%4];\n"
                    : "=r"(bf[2 * p][0]), "=r"(bf[2 * p][1]),
                      "=r"(bf[2 * p + 1][0]), "=r"(bf[2 * p + 1][1])
                    : "r"(addr));
            }
            #pragma unroll
            for (int mt = 0; mt < 4; ++mt) {
                #pragma unroll
                for (int nt = 0; nt < 8; ++nt) {
                    asm volatile(
                        "mma.sync.aligned.m16n8k16.row.col.f32.f16.f16.f32 "
                        "{%0,%1,%2,%3}, {%4,%5,%6,%7}, {%8,%9}, {%0,%1,%2,%3};\n"
                        : "+f"(acc[mt][nt][0]), "+f"(acc[mt][nt][1]),
                          "+f"(acc[mt][nt][2]), "+f"(acc[mt][nt][3])
                        : "r"(af[mt][0]), "r"(af[mt][1]),
                          "r"(af[mt][2]), "r"(af[mt][3]),
                          "r"(bf[nt][0]), "r"(bf[nt][1]));
                }
            }
        }
    };

    // prologue: fill stages 0..1
    #pragma unroll
    for (int s = 0; s < STAGES - 1; ++s) {
        load_stage(s, s);
        cp_commit();
    }

    // mainloop
    #pragma unroll 1
    for (int kt = 0; kt < KTILES; ++kt) {
        const int cs = kt % STAGES;
        cp_wait<STAGES - 2>();
        __syncthreads();
        const int pf = kt + STAGES - 1;
        if (pf < KTILES) load_stage(pf % STAGES, pf);
        cp_commit();
        mma_stage(cs);
    }

    // epilogue: out = acc*scale + bias
    const float scl = __ldg(scale_p);
    const int mBase = mRow0 + warp_m * 64;
    const int nBase = nCol0 + warp_n * 64;
    const int rl = lane >> 2;
    const int cl = (lane & 3) * 2;
    #pragma unroll
    for (int mt = 0; mt < 4; ++mt) {
        #pragma unroll
        for (int nt = 0; nt < 8; ++nt) {
            int c = nBase + nt * 8 + cl;
            float2 bv = *reinterpret_cast<const float2*>(bias + c);
            int r0 = mBase + mt * 16 + rl;
            float2 v0 = make_float2(acc[mt][nt][0] * scl + bv.x,
                                    acc[mt][nt][1] * scl + bv.y);
            *reinterpret_cast<float2*>(out + (size_t)r0 * N_DIM + c) = v0;
            float2 v1 = make_float2(acc[mt][nt][2] * scl + bv.x,
                                    acc[mt][nt][3] * scl + bv.y);
            *reinterpret_cast<float2*>(out + (size_t)(r0 + 8) * N_DIM + c) = v1;
        }
    }
}

// ---------------------------------------------------------------------------
// Launch
// ---------------------------------------------------------------------------
extern "C" void kernel_launch(void* const* d_in, const int* in_sizes, int n_in,
                              void* d_out, int out_size) {
    const float* x     = (const float*)d_in[0];
    const int*   w     = (const int*)d_in[1];
    const float* scale = (const float*)d_in[2];
    const float* bias  = (const float*)d_in[3];
    float* out = (float*)d_out;

    cudaFuncSetAttribute(gemm_kernel,
                         cudaFuncAttributeMaxDynamicSharedMemorySize,
                         SMEM_BYTES);

    // x: 16,777,216 elems / 4096 per block = 4096 blocks (exact)
    convert_x_kernel<<<4096, 256>>>(x);
    // w: 45,088,768 elems / 4096 per block = 11008 blocks (exact)
    convert_w_kernel<<<11008, 256>>>(w);

    dim3 grid(N_DIM / BN, M_DIM / BM);   // (43, 32)
    gemm_kernel<<<grid, NTHREADS, SMEM_BYTES>>>(scale, bias, out);
}

// round 7
// speedup vs baseline: 1.0448x; 1.0448x over previous
#include <cuda_runtime.h>
#include <cuda_fp16.h>
#include <cstdint>
#include <cstddef>

// ---------------------------------------------------------------------------
// CompressedLinear (plain-sm_100 target: mma.sync is the only tensor path).
//   out[4096, 11008] = x_f16[4096,4096] @ (w_f16[11008,4096])^T * scale + bias
//
// GEMM: block tile 128(M) x 256(N) x 64(K), 4-stage cp.async pipeline,
// 16 warps (512 thr), warp tile 64x32 (2 M-warps x 8 N-warps),
// mma.sync.m16n8k16 fp16 -> fp32. 1 CTA/SM, 16 warps/SM = 4 per SMSP.
// ---------------------------------------------------------------------------

namespace {
constexpr int M_DIM = 4096;
constexpr int K_DIM = 4096;
constexpr int N_DIM = 11008;

constexpr int BM = 128;
constexpr int BN = 256;
constexpr int BK = 64;
constexpr int STAGES = 4;
constexpr int NTHREADS = 512;
constexpr int KTILES = K_DIM / BK;                 // 64

constexpr int A_STAGE_BYTES = BM * BK * 2;         // 16 KB
constexpr int B_STAGE_BYTES = BN * BK * 2;         // 32 KB
constexpr int STAGE_BYTES   = A_STAGE_BYTES + B_STAGE_BYTES;   // 48 KB
constexpr int SMEM_BYTES    = STAGES * STAGE_BYTES;            // 192 KB
}

// fp16 scratch (allocation-free rule: __device__ globals)
__device__ __half g_X[(size_t)M_DIM * K_DIM];   // 32 MB [M,K]
__device__ __half g_W[(size_t)N_DIM * K_DIM];   // 90 MB [N,K]

// ---------------------------------------------------------------------------
// Conversion kernels: 4 independent float4/int4 loads per thread (MLP=4)
// ---------------------------------------------------------------------------
__global__ void convert_x_kernel(const float* __restrict__ x) {
    size_t blk = (size_t)blockIdx.x * 4096;
    #pragma unroll
    for (int t = 0; t < 4; ++t) {
        size_t i = blk + (size_t)t * 1024 + threadIdx.x * 4;
        float4 v = *reinterpret_cast<const float4*>(x + i);
        __half2 h0 = __floats2half2_rn(v.x, v.y);
        __half2 h1 = __floats2half2_rn(v.z, v.w);
        uint2 u;
        u.x = reinterpret_cast<uint32_t&>(h0);
        u.y = reinterpret_cast<uint32_t&>(h1);
        *reinterpret_cast<uint2*>(&g_X[i]) = u;
    }
}

__global__ void convert_w_kernel(const int* __restrict__ w) {
    size_t blk = (size_t)blockIdx.x * 4096;
    #pragma unroll
    for (int t = 0; t < 4; ++t) {
        size_t i = blk + (size_t)t * 1024 + threadIdx.x * 4;
        int4 v = *reinterpret_cast<const int4*>(w + i);
        __half2 h0 = __halves2half2(__int2half_rn(v.x), __int2half_rn(v.y));
        __half2 h1 = __halves2half2(__int2half_rn(v.z), __int2half_rn(v.w));
        uint2 u;
        u.x = reinterpret_cast<uint32_t&>(h0);
        u.y = reinterpret_cast<uint32_t&>(h1);
        *reinterpret_cast<uint2*>(&g_W[i]) = u;
    }
}

// ---------------------------------------------------------------------------
// Helpers
// ---------------------------------------------------------------------------
__device__ __forceinline__ uint32_t swz128(uint32_t b) {
    return b ^ ((b >> 3) & 0x70);
}
__device__ __forceinline__ void cp_async16(uint32_t dst, const void* src) {
    asm volatile("cp.async.cg.shared.global [%0], [%1], 16;\n" :: "r"(dst), "l"(src));
}
__device__ __forceinline__ void cp_commit() {
    asm volatile("cp.async.commit_group;\n");
}
template <int N>
__device__ __forceinline__ void cp_wait() {
    asm volatile("cp.async.wait_group %0;\n" :: "n"(N));
}

// ---------------------------------------------------------------------------
// GEMM kernel
// ---------------------------------------------------------------------------
__global__ __launch_bounds__(NTHREADS, 1)
void gemm_kernel(const float* __restrict__ scale_p,
                 const float* __restrict__ bias,
                 float* __restrict__ out) {
    extern __shared__ __align__(128) char smem_raw[];
    const uint32_t smem_base = (uint32_t)__cvta_generic_to_shared(smem_raw);

    const int tid  = threadIdx.x;
    const int warp = tid >> 5;
    const int lane = tid & 31;
    const int bx = blockIdx.x;            // N block (0..42)
    const int by = blockIdx.y;            // M block (0..31)

    const int warp_m = warp & 1;          // 0..1  (64 rows each)
    const int warp_n = warp >> 1;         // 0..7  (32 cols each)

    const int mRow0 = by * BM;
    const int nCol0 = bx * BN;

    float acc[4][4][4];
    #pragma unroll
    for (int i = 0; i < 4; ++i)
        #pragma unroll
        for (int j = 0; j < 4; ++j)
            #pragma unroll
            for (int k = 0; k < 4; ++k)
                acc[i][j][k] = 0.0f;

    // stage loader: A 1024 chunks (2/thread) + B 2048 chunks (4/thread)
    auto load_stage = [&](int s, int kt) {
        const uint32_t aB = smem_base + s * STAGE_BYTES;
        const uint32_t bB = aB + A_STAGE_BYTES;
        const int k0 = kt * BK;
        #pragma unroll
        for (int t = 0; t < 2; ++t) {
            int c   = tid + t * NTHREADS;      // 0..1023
            int row = c >> 3;                  // 0..127
            int col = c & 7;
            uint32_t off = swz128((uint32_t)(row * 128 + col * 16));
            cp_async16(aB + off, &g_X[(size_t)(mRow0 + row) * K_DIM + k0 + col * 8]);
        }
        #pragma unroll
        for (int t = 0; t < 4; ++t) {
            int c   = tid + t * NTHREADS;      // 0..2047
            int row = c >> 3;                  // 0..255
            int col = c & 7;
            uint32_t off = swz128((uint32_t)(row * 128 + col * 16));
            cp_async16(bB + off, &g_W[(size_t)(nCol0 + row) * K_DIM + k0 + col * 8]);
        }
    };

    // compute one K-tile from stage s (proven Round-1 64x32 warp mapping)
    auto mma_stage = [&](int s) {
        const uint32_t aB = smem_base + s * STAGE_BYTES;
        const uint32_t bB = aB + A_STAGE_BYTES;
        #pragma unroll
        for (int ks = 0; ks < BK / 16; ++ks) {
            uint32_t af[4][4];
            uint32_t bf[4][2];
            #pragma unroll
            for (int mt = 0; mt < 4; ++mt) {
                int r = warp_m * 64 + mt * 16 + (lane & 15);
                uint32_t addr = aB +
                    swz128((uint32_t)(r * 128 + ks * 32 + (lane >> 4) * 16));
                asm volatile(
                    "ldmatrix.sync.aligned.m8n8.x4.shared.b16 {%0,%1,%2,%3}, [%4];\n"
                    : "=r"(af[mt][0]), "=r"(af[mt][1]),
                      "=r"(af[mt][2]), "=r"(af[mt][3])
                    : "r"(addr));
            }
            #pragma unroll
            for (int p = 0; p < 2; ++p) {
                int n  = warp_n * 32 + p * 16 + (lane & 7) + ((lane >> 4) << 3);
                int kc = (lane >> 3) & 1;
                uint32_t addr = bB +
                    swz128((uint32_t)(n * 128 + ks * 32 + kc * 16));
                asm volatile(
                    "ldmatrix.sync.aligned.m8n8.x4.shared.b16 {%0,%1,%2,%3}, [%4];\n"
                    : "=r"(bf[2 * p][0]), "=r"(bf[2 * p][1]),
                      "=r"(bf[2 * p + 1][0]), "=r"(bf[2 * p + 1][1])
                    : "r"(addr));
            }
            #pragma unroll
            for (int mt = 0; mt < 4; ++mt) {
                #pragma unroll
                for (int nt = 0; nt < 4; ++nt) {
                    asm volatile(
                        "mma.sync.aligned.m16n8k16.row.col.f32.f16.f16.f32 "
                        "{%0,%1,%2,%3}, {%4,%5,%6,%7}, {%8,%9}, {%0,%1,%2,%3};\n"
                        : "+f"(acc[mt][nt][0]), "+f"(acc[mt][nt][1]),
                          "+f"(acc[mt][nt][2]), "+f"(acc[mt][nt][3])
                        : "r"(af[mt][0]), "r"(af[mt][1]),
                          "r"(af[mt][2]), "r"(af[mt][3]),
                          "r"(bf[nt][0]), "r"(bf[nt][1]));
                }
            }
        }
    };

    // prologue: fill stages 0..2
    #pragma unroll
    for (int s = 0; s < STAGES - 1; ++s) {
        load_stage(s, s);
        cp_commit();
    }

    // mainloop
    #pragma unroll 1
    for (int kt = 0; kt < KTILES; ++kt) {
        const int cs = kt & (STAGES - 1);
        cp_wait<STAGES - 2>();
        __syncthreads();
        const int pf = kt + STAGES - 1;
        if (pf < KTILES) load_stage(pf & (STAGES - 1), pf);
        cp_commit();
        mma_stage(cs);
    }

    // epilogue: out = acc*scale + bias
    const float scl = __ldg(scale_p);
    const int mBase = mRow0 + warp_m * 64;
    const int nBase = nCol0 + warp_n * 32;
    const int rl = lane >> 2;
    const int cl = (lane & 3) * 2;
    #pragma unroll
    for (int mt = 0; mt < 4; ++mt) {
        #pragma unroll
        for (int nt = 0; nt < 4; ++nt) {
            int c = nBase + nt * 8 + cl;
            float2 bv = *reinterpret_cast<const float2*>(bias + c);
            int r0 = mBase + mt * 16 + rl;
            float2 v0 = make_float2(acc[mt][nt][0] * scl + bv.x,
                                    acc[mt][nt][1] * scl + bv.y);
            *reinterpret_cast<float2*>(out + (size_t)r0 * N_DIM + c) = v0;
            float2 v1 = make_float2(acc[mt][nt][2] * scl + bv.x,
                                    acc[mt][nt][3] * scl + bv.y);
            *reinterpret_cast<float2*>(out + (size_t)(r0 + 8) * N_DIM + c) = v1;
        }
    }
}

// ---------------------------------------------------------------------------
// Launch
// ---------------------------------------------------------------------------
extern "C" void kernel_launch(void* const* d_in, const int* in_sizes, int n_in,
                              void* d_out, int out_size) {
    const float* x     = (const float*)d_in[0];
    const int*   w     = (const int*)d_in[1];
    const float* scale = (const float*)d_in[2];
    const float* bias  = (const float*)d_in[3];
    float* out = (float*)d_out;

    cudaFuncSetAttribute(gemm_kernel,
                         cudaFuncAttributeMaxDynamicSharedMemorySize,
                         SMEM_BYTES);

    convert_x_kernel<<<4096, 256>>>(x);
    convert_w_kernel<<<11008, 256>>>(w);

    dim3 grid(N_DIM / BN, M_DIM / BM);   // (43, 32)
    gemm_kernel<<<grid, NTHREADS, SMEM_BYTES>>>(scale, bias, out);
}

// round 8
// speedup vs baseline: 1.1239x; 1.0756x over previous
#include <cuda_runtime.h>
#include <cuda_fp16.h>
#include <cstdint>
#include <cstddef>

// ---------------------------------------------------------------------------
// CompressedLinear (plain-sm_100 target: mma.sync is the only tensor path).
//   out[4096, 11008] = x_f16[4096,4096] @ (w_f16[11008,4096])^T * scale + bias
//
// GEMM: proven R1 config — block tile 128x128x64, 3-stage cp.async pipeline,
// 8 warps (256 thr), warp tile 64x32, 2 CTAs/SM (two independent pipelines
// per SM; this decoupling measured faster than any 1-CTA/SM variant).
// Grid is M-fastest so concurrent CTAs form complete N-columns: each column
// shares its W block in L2 and X (32 MB fp16) stays L2-resident.
// ---------------------------------------------------------------------------

namespace {
constexpr int M_DIM = 4096;
constexpr int K_DIM = 4096;
constexpr int N_DIM = 11008;

constexpr int BM = 128;
constexpr int BN = 128;
constexpr int BK = 64;
constexpr int STAGES = 3;
constexpr int NTHREADS = 256;
constexpr int KTILES = K_DIM / BK;                 // 64

constexpr int A_STAGE_BYTES = BM * BK * 2;         // 16 KB
constexpr int B_STAGE_BYTES = BN * BK * 2;         // 16 KB
constexpr int STAGE_BYTES   = A_STAGE_BYTES + B_STAGE_BYTES;   // 32 KB
constexpr int SMEM_BYTES    = STAGES * STAGE_BYTES;            // 96 KB
}

// fp16 scratch (allocation-free rule: __device__ globals)
__device__ __half g_X[(size_t)M_DIM * K_DIM];   // 32 MB [M,K]
__device__ __half g_W[(size_t)N_DIM * K_DIM];   // 90 MB [N,K]

// ---------------------------------------------------------------------------
// Conversion kernels: 4 independent float4/int4 loads per thread (MLP=4)
// ---------------------------------------------------------------------------
__global__ void convert_x_kernel(const float* __restrict__ x) {
    size_t blk = (size_t)blockIdx.x * 4096;
    #pragma unroll
    for (int t = 0; t < 4; ++t) {
        size_t i = blk + (size_t)t * 1024 + threadIdx.x * 4;
        float4 v = *reinterpret_cast<const float4*>(x + i);
        __half2 h0 = __floats2half2_rn(v.x, v.y);
        __half2 h1 = __floats2half2_rn(v.z, v.w);
        uint2 u;
        u.x = reinterpret_cast<uint32_t&>(h0);
        u.y = reinterpret_cast<uint32_t&>(h1);
        *reinterpret_cast<uint2*>(&g_X[i]) = u;
    }
}

__global__ void convert_w_kernel(const int* __restrict__ w) {
    size_t blk = (size_t)blockIdx.x * 4096;
    #pragma unroll
    for (int t = 0; t < 4; ++t) {
        size_t i = blk + (size_t)t * 1024 + threadIdx.x * 4;
        int4 v = *reinterpret_cast<const int4*>(w + i);
        __half2 h0 = __halves2half2(__int2half_rn(v.x), __int2half_rn(v.y));
        __half2 h1 = __halves2half2(__int2half_rn(v.z), __int2half_rn(v.w));
        uint2 u;
        u.x = reinterpret_cast<uint32_t&>(h0);
        u.y = reinterpret_cast<uint32_t&>(h1);
        *reinterpret_cast<uint2*>(&g_W[i]) = u;
    }
}

// ---------------------------------------------------------------------------
// Helpers
// ---------------------------------------------------------------------------
__device__ __forceinline__ uint32_t swz128(uint32_t b) {
    return b ^ ((b >> 3) & 0x70);
}
__device__ __forceinline__ void cp_async16(uint32_t dst, const void* src) {
    asm volatile("cp.async.cg.shared.global [%0], [%1], 16;\n" :: "r"(dst), "l"(src));
}
__device__ __forceinline__ void cp_commit() {
    asm volatile("cp.async.commit_group;\n");
}
template <int N>
__device__ __forceinline__ void cp_wait() {
    asm volatile("cp.async.wait_group %0;\n" :: "n"(N));
}

// ---------------------------------------------------------------------------
// GEMM kernel: 128x128x64 block, 8 warps (2 M x 4 N), warp tile 64x32,
// mma.sync.m16n8k16 fp16->fp32, 2 CTAs/SM.
// ---------------------------------------------------------------------------
__global__ __launch_bounds__(NTHREADS, 2)
void gemm_kernel(const float* __restrict__ scale_p,
                 const float* __restrict__ bias,
                 float* __restrict__ out) {
    extern __shared__ __align__(128) char smem_raw[];
    const uint32_t smem_base = (uint32_t)__cvta_generic_to_shared(smem_raw);

    const int tid  = threadIdx.x;
    const int warp = tid >> 5;
    const int lane = tid & 31;
    const int mTile = blockIdx.x;   // M block (0..31)  -- fastest: N-columns run concurrently
    const int nTile = blockIdx.y;   // N block (0..85)

    const int warp_m = warp & 1;    // 0..1  (64 rows each)
    const int warp_n = warp >> 1;   // 0..3  (32 cols each)

    const int mRow0 = mTile * BM;
    const int nCol0 = nTile * BN;

    float acc[4][4][4];
    #pragma unroll
    for (int i = 0; i < 4; ++i)
        #pragma unroll
        for (int j = 0; j < 4; ++j)
            #pragma unroll
            for (int k = 0; k < 4; ++k)
                acc[i][j][k] = 0.0f;

    // stage loader: 1024 16B chunks per operand, 256 threads -> 4 each
    auto load_stage = [&](int s, int kt) {
        const uint32_t aBase = smem_base + s * STAGE_BYTES;
        const uint32_t bBase = aBase + A_STAGE_BYTES;
        const int k0 = kt * BK;
        #pragma unroll
        for (int t = 0; t < 4; ++t) {
            int c   = tid + t * NTHREADS;     // 0..1023
            int row = c >> 3;                 // 0..127
            int col = c & 7;
            uint32_t off = swz128((uint32_t)(row * 128 + col * 16));
            cp_async16(aBase + off,
                       &g_X[(size_t)(mRow0 + row) * K_DIM + k0 + col * 8]);
        }
        #pragma unroll
        for (int t = 0; t < 4; ++t) {
            int c   = tid + t * NTHREADS;
            int row = c >> 3;
            int col = c & 7;
            uint32_t off = swz128((uint32_t)(row * 128 + col * 16));
            cp_async16(bBase + off,
                       &g_W[(size_t)(nCol0 + row) * K_DIM + k0 + col * 8]);
        }
    };

    // compute one K-tile from stage s
    auto mma_stage = [&](int s) {
        const uint32_t aBase = smem_base + s * STAGE_BYTES;
        const uint32_t bBase = aBase + A_STAGE_BYTES;
        #pragma unroll
        for (int ks = 0; ks < BK / 16; ++ks) {
            uint32_t af[4][4];
            uint32_t bf[4][2];
            #pragma unroll
            for (int mt = 0; mt < 4; ++mt) {
                int r = warp_m * 64 + mt * 16 + (lane & 15);
                uint32_t addr = aBase +
                    swz128((uint32_t)(r * 128 + ks * 32 + (lane >> 4) * 16));
                asm volatile(
                    "ldmatrix.sync.aligned.m8n8.x4.shared.b16 {%0,%1,%2,%3}, [%4];\n"
                    : "=r"(af[mt][0]), "=r"(af[mt][1]),
                      "=r"(af[mt][2]), "=r"(af[mt][3])
                    : "r"(addr));
            }
            #pragma unroll
            for (int p = 0; p < 2; ++p) {
                int n  = warp_n * 32 + p * 16 + (lane & 7) + ((lane >> 4) << 3);
                int kc = (lane >> 3) & 1;
                uint32_t addr = bBase +
                    swz128((uint32_t)(n * 128 + ks * 32 + kc * 16));
                asm volatile(
                    "ldmatrix.sync.aligned.m8n8.x4.shared.b16 {%0,%1,%2,%3}, [%4];\n"
                    : "=r"(bf[2 * p][0]), "=r"(bf[2 * p][1]),
                      "=r"(bf[2 * p + 1][0]), "=r"(bf[2 * p + 1][1])
                    : "r"(addr));
            }
            #pragma unroll
            for (int mt = 0; mt < 4; ++mt) {
                #pragma unroll
                for (int nt = 0; nt < 4; ++nt) {
                    asm volatile(
                        "mma.sync.aligned.m16n8k16.row.col.f32.f16.f16.f32 "
                        "{%0,%1,%2,%3}, {%4,%5,%6,%7}, {%8,%9}, {%0,%1,%2,%3};\n"
                        : "+f"(acc[mt][nt][0]), "+f"(acc[mt][nt][1]),
                          "+f"(acc[mt][nt][2]), "+f"(acc[mt][nt][3])
                        : "r"(af[mt][0]), "r"(af[mt][1]),
                          "r"(af[mt][2]), "r"(af[mt][3]),
                          "r"(bf[nt][0]), "r"(bf[nt][1]));
                }
            }
        }
    };

    // prologue: fill STAGES-1 stages
    #pragma unroll
    for (int s = 0; s < STAGES - 1; ++s) {
        load_stage(s, s);
        cp_commit();
    }

    // mainloop
    int cs = 0;              // compute stage
    int ps = STAGES - 1;     // prefetch stage
    #pragma unroll 1
    for (int kt = 0; kt < KTILES; ++kt) {
        cp_wait<STAGES - 2>();
        __syncthreads();
        int pf = kt + STAGES - 1;
        if (pf < KTILES) load_stage(ps, pf);
        cp_commit();
        mma_stage(cs);
        if (++cs == STAGES) cs = 0;
        if (++ps == STAGES) ps = 0;
    }

    // epilogue: out = acc*scale + bias
    const float scl = __ldg(scale_p);
    const int mBase = mRow0 + warp_m * 64;
    const int nBase = nCol0 + warp_n * 32;
    const int rl = lane >> 2;
    const int cl = (lane & 3) * 2;
    #pragma unroll
    for (int mt = 0; mt < 4; ++mt) {
        #pragma unroll
        for (int nt = 0; nt < 4; ++nt) {
            int c = nBase + nt * 8 + cl;
            float2 bv = *reinterpret_cast<const float2*>(bias + c);
            int r0 = mBase + mt * 16 + rl;
            float2 v0 = make_float2(acc[mt][nt][0] * scl + bv.x,
                                    acc[mt][nt][1] * scl + bv.y);
            *reinterpret_cast<float2*>(out + (size_t)r0 * N_DIM + c) = v0;
            float2 v1 = make_float2(acc[mt][nt][2] * scl + bv.x,
                                    acc[mt][nt][3] * scl + bv.y);
            *reinterpret_cast<float2*>(out + (size_t)(r0 + 8) * N_DIM + c) = v1;
        }
    }
}

// ---------------------------------------------------------------------------
// Launch
// ---------------------------------------------------------------------------
extern "C" void kernel_launch(void* const* d_in, const int* in_sizes, int n_in,
                              void* d_out, int out_size) {
    const float* x     = (const float*)d_in[0];
    const int*   w     = (const int*)d_in[1];
    const float* scale = (const float*)d_in[2];
    const float* bias  = (const float*)d_in[3];
    float* out = (float*)d_out;

    cudaFuncSetAttribute(gemm_kernel,
                         cudaFuncAttributeMaxDynamicSharedMemorySize,
                         SMEM_BYTES);

    convert_x_kernel<<<4096, 256>>>(x);
    convert_w_kernel<<<11008, 256>>>(w);

    dim3 grid(M_DIM / BM, N_DIM / BN);   // (32, 86) -- M fastest
    gemm_kernel<<<grid, NTHREADS, SMEM_BYTES>>>(scale, bias, out);
}